// round 14
// baseline (speedup 1.0000x reference)
#include <cuda_runtime.h>
#include <cuda_fp16.h>
#include <cstdint>

// ---------------- constants ----------------
constexpr int THREADS = 256;     // 8 autonomous warps, each owns 16 edges/tile
constexpr int NWARP   = 8;

constexpr int LDX   = 200;  // X16 stride (halfs): 400B
constexpr int LDK1  = 200;  // W1n^T fp16 stride (halfs)
constexpr int LDW8  = 208;  // W1e fp8 stride (bytes)
constexpr int LDX8  = 208;  // X8 stride (bytes)
constexpr int LDK2  = 72;   // W2^T fp16 stride (halfs)
constexpr int LDKR  = 24;   // Wrbf^T stride (halfs)
constexpr int LDRB  = 24;   // rbf activation stride (halfs)

// byte offsets into dynamic smem
constexpr int B_W1E8 = 0;                         // [128 n][208B] fp8 (l|g), x16 scaled
constexpr int B_W1N  = B_W1E8 + 128*LDW8;         // [128 n][200h] fp16 (l|g), K=192
constexpr int B_W2E  = B_W1N  + 128*LDK1*2;       // [128 n][72h] fp16
constexpr int B_W2N  = B_W2E  + 128*LDK2*2;
constexpr int B_WRB  = B_W2N  + 128*LDK2*2;       // [128 n][24h] (We|Wn, k9..15=0)
constexpr int B_B1E  = B_WRB  + 128*LDKR*2;       // [128] float each
constexpr int B_B2E  = B_B1E + 128*4;
constexpr int B_B1N  = B_B2E + 128*4;
constexpr int B_B2N  = B_B1N + 128*4;
constexpr int B_X16  = B_B2N + 128*4;             // 8 x [16][200h] fp16 (vi|vj|ef->e_new)
constexpr int B_X8   = B_X16 + NWARP*16*LDX*2;    // 8 x [16][208B] fp8 (vi|vj|ef)
constexpr int B_RB   = B_X8  + NWARP*16*LDX8;     // 8 x [16][24h]
constexpr int SMEM_BYTES = B_RB + NWARP*16*LDRB*2;  // = 206,848

__device__ __forceinline__ float fsig(float x) {
    float t;
    asm("tanh.approx.f32 %0, %1;\n" : "=f"(t) : "f"(x * 0.5f));
    return fmaf(t, 0.5f, 0.5f);
}
__device__ __forceinline__ float fsilu(float x) { return x * fsig(x); }

__device__ __forceinline__ uint32_t cvta_s(const void* p) {
    return (uint32_t)__cvta_generic_to_shared(p);
}
__device__ __forceinline__ void ldx4(uint32_t* r, uint32_t a) {
    asm volatile("ldmatrix.sync.aligned.m8n8.x4.shared.b16 {%0,%1,%2,%3}, [%4];\n"
                 : "=r"(r[0]), "=r"(r[1]), "=r"(r[2]), "=r"(r[3]) : "r"(a));
}
__device__ __forceinline__ void mma16816(float* c, const uint32_t* a, uint32_t b0, uint32_t b1) {
    asm volatile("mma.sync.aligned.m16n8k16.row.col.f32.f16.f16.f32 "
                 "{%0,%1,%2,%3}, {%4,%5,%6,%7}, {%8,%9}, {%0,%1,%2,%3};\n"
                 : "+f"(c[0]), "+f"(c[1]), "+f"(c[2]), "+f"(c[3])
                 : "r"(a[0]), "r"(a[1]), "r"(a[2]), "r"(a[3]), "r"(b0), "r"(b1));
}
__device__ __forceinline__ void mma16832(float* c, const uint32_t* a, uint32_t b0, uint32_t b1) {
    asm volatile("mma.sync.aligned.m16n8k32.row.col.f32.e4m3.e4m3.f32 "
                 "{%0,%1,%2,%3}, {%4,%5,%6,%7}, {%8,%9}, {%0,%1,%2,%3};\n"
                 : "+f"(c[0]), "+f"(c[1]), "+f"(c[2]), "+f"(c[3])
                 : "r"(a[0]), "r"(a[1]), "r"(a[2]), "r"(a[3]), "r"(b0), "r"(b1));
}
__device__ __forceinline__ uint32_t h2pack(float a, float b) {
    __half2 h = __floats2half2_rn(a, b);
    return *(uint32_t*)&h;
}
__device__ __forceinline__ void st4h(__half* p, float4 v) {
    uint2 u;
    u.x = h2pack(v.x, v.y);
    u.y = h2pack(v.z, v.w);
    *(uint2*)p = u;
}
// pack 4 floats -> 4 e4m3 bytes (byte0 = a)
__device__ __forceinline__ uint32_t f4_e4m3(float a, float b, float c, float d) {
    uint16_t lo, hi;
    asm("cvt.rn.satfinite.e4m3x2.f32 %0, %1, %2;" : "=h"(lo) : "f"(b), "f"(a));
    asm("cvt.rn.satfinite.e4m3x2.f32 %0, %1, %2;" : "=h"(hi) : "f"(d), "f"(c));
    return (uint32_t)lo | ((uint32_t)hi << 16);
}
__device__ __forceinline__ uint4 q16(const float4* v) {
    uint4 o;
    float4 a = v[0], b = v[1], c = v[2], d = v[3];
    o.x = f4_e4m3(a.x, a.y, a.z, a.w);
    o.y = f4_e4m3(b.x, b.y, b.z, b.w);
    o.z = f4_e4m3(c.x, c.y, c.z, c.w);
    o.w = f4_e4m3(d.x, d.y, d.z, d.w);
    return o;
}

// ================= EDGE GEMM1: fp8, m16 x n128 x k192 (6 kt of k32) ==========
// weights pre-scaled x16; acc rescaled x1/16 before bias+silu.
__device__ __forceinline__ void gemm1_e8(const uint8_t* X8, const uint8_t* W8,
                                         const float* b1, uint32_t* ah, uint32_t* ag, int lane)
{
    float acc[16][4];
    #pragma unroll
    for (int n = 0; n < 16; ++n)
        #pragma unroll
        for (int j = 0; j < 4; ++j) acc[n][j] = 0.0f;

    uint32_t aB = cvta_s(X8 + (lane & 15) * LDX8 + ((lane >> 4) << 4));
    const int n_off = (lane & 7) + ((lane >> 4) << 3);
    const int k_off = ((lane >> 3) & 1) << 4;
    uint32_t bB = cvta_s(W8 + n_off * LDW8 + k_off);

    #pragma unroll
    for (int kt = 0; kt < 6; ++kt) {
        uint32_t a[4];
        ldx4(a, aB + kt * 32);
        #pragma unroll
        for (int nb2 = 0; nb2 < 8; ++nb2) {
            uint32_t b[4];
            ldx4(b, bB + nb2 * 16 * LDW8 + kt * 32);
            mma16832(acc[2*nb2],     a, b[0], b[1]);
            mma16832(acc[2*nb2 + 1], a, b[2], b[3]);
        }
    }

    const int cp = (lane & 3) << 1;
    #pragma unroll
    for (int nb = 0; nb < 16; ++nb) {
        int c = nb * 8 + cp;
        float v0 = fsilu(fmaf(acc[nb][0], 0.0625f, b1[c]));
        float v1 = fsilu(fmaf(acc[nb][1], 0.0625f, b1[c + 1]));
        float v2 = fsilu(fmaf(acc[nb][2], 0.0625f, b1[c]));
        float v3 = fsilu(fmaf(acc[nb][3], 0.0625f, b1[c + 1]));
        uint32_t* dstv = (nb < 8) ? ah : ag;
        int kb = (nb & 7) >> 1, odd = nb & 1;
        dstv[kb*4 + odd*2 + 0] = h2pack(v0, v1);
        dstv[kb*4 + odd*2 + 1] = h2pack(v2, v3);
    }
}

// ================= NODE GEMM1: fp16, m16 x n128 x k192 (champion code) =======
__device__ __forceinline__ void gemm1_reg(const __half* X, const __half* W1,
                                          const float* bias,
                                          uint32_t* ah, uint32_t* ag, int lane)
{
    float acc[16][4];
    #pragma unroll
    for (int n = 0; n < 16; ++n)
        #pragma unroll
        for (int j = 0; j < 4; ++j) acc[n][j] = 0.0f;

    uint32_t aB = cvta_s(X + (lane & 15) * LDX + ((lane >> 4) << 3));
    const int n_off = (lane & 7) + ((lane >> 4) << 3);
    const int k_off = ((lane >> 3) & 1) << 3;
    uint32_t bB = cvta_s(W1 + n_off * LDK1 + k_off);

    #pragma unroll
    for (int kt = 0; kt < 12; ++kt) {
        uint32_t a[4];
        ldx4(a, aB + kt * 32);
        #pragma unroll
        for (int nb2 = 0; nb2 < 8; ++nb2) {
            uint32_t b[4];
            ldx4(b, bB + (nb2 * 16 * LDK1 + kt * 16) * 2);
            mma16816(acc[2*nb2],     a, b[0], b[1]);
            mma16816(acc[2*nb2 + 1], a, b[2], b[3]);
        }
    }

    const int cp = (lane & 3) << 1;
    #pragma unroll
    for (int nb = 0; nb < 16; ++nb) {
        int c = nb * 8 + cp;
        float v0 = fsilu(acc[nb][0] + bias[c]);
        float v1 = fsilu(acc[nb][1] + bias[c + 1]);
        float v2 = fsilu(acc[nb][2] + bias[c]);
        float v3 = fsilu(acc[nb][3] + bias[c + 1]);
        uint32_t* dstv = (nb < 8) ? ah : ag;
        int kb = (nb & 7) >> 1, odd = nb & 1;
        dstv[kb*4 + odd*2 + 0] = h2pack(v0, v1);
        dstv[kb*4 + odd*2 + 1] = h2pack(v2, v3);
    }
}

// GEMM2 (H & G, A in regs) + rbf mini-GEMM + gate combine (champion code).
template <int PATH>
__device__ __forceinline__ void tail_reg(const uint32_t* ah, const uint32_t* ag,
                                         const __half* W2, const float* b2,
                                         const __half* RB, const __half* WRB,
                                         float u[8][4], int lane)
{
    float acch[8][4], accg[8][4];
    #pragma unroll
    for (int n = 0; n < 8; ++n)
        #pragma unroll
        for (int j = 0; j < 4; ++j) { acch[n][j] = 0; accg[n][j] = 0; }

    const int n_off = (lane & 7) + ((lane >> 4) << 3);
    const int k_off = ((lane >> 3) & 1) << 3;
    uint32_t bB = cvta_s(W2 + n_off * LDK2 + k_off);

    #pragma unroll
    for (int kt = 0; kt < 4; ++kt) {
        #pragma unroll
        for (int nb2 = 0; nb2 < 4; ++nb2) {
            uint32_t b[4];
            ldx4(b, bB + (nb2 * 16 * LDK2 + kt * 16) * 2);
            mma16816(acch[2*nb2],     ah + kt*4, b[0], b[1]);
            mma16816(acch[2*nb2 + 1], ah + kt*4, b[2], b[3]);
        }
        #pragma unroll
        for (int nb2 = 0; nb2 < 4; ++nb2) {
            uint32_t b[4];
            ldx4(b, bB + ((64 + nb2 * 16) * LDK2 + kt * 16) * 2);
            mma16816(accg[2*nb2],     ag + kt*4, b[0], b[1]);
            mma16816(accg[2*nb2 + 1], ag + kt*4, b[2], b[3]);
        }
    }

    float accr[8][4];
    #pragma unroll
    for (int n = 0; n < 8; ++n)
        #pragma unroll
        for (int j = 0; j < 4; ++j) accr[n][j] = 0;
    {
        uint32_t ar[4];
        ldx4(ar, cvta_s(RB + (lane & 15) * LDRB + ((lane >> 4) << 3)));
        uint32_t bR = cvta_s(WRB + (PATH * 64 + n_off) * LDKR + k_off);
        #pragma unroll
        for (int nb2 = 0; nb2 < 4; ++nb2) {
            uint32_t b[4];
            ldx4(b, bR + (nb2 * 16 * LDKR) * 2);
            mma16816(accr[2*nb2],     ar, b[0], b[1]);
            mma16816(accr[2*nb2 + 1], ar, b[2], b[3]);
        }
    }

    const int cp = (lane & 3) << 1;
    #pragma unroll
    for (int ob = 0; ob < 8; ++ob) {
        int c = ob * 8 + cp;
        float bh0 = b2[c], bh1 = b2[c + 1];
        float bg0 = b2[64 + c], bg1 = b2[64 + c + 1];
        u[ob][0] = fsilu(acch[ob][0] + bh0) * fsig(accg[ob][0] + bg0) * accr[ob][0];
        u[ob][1] = fsilu(acch[ob][1] + bh1) * fsig(accg[ob][1] + bg1) * accr[ob][1];
        u[ob][2] = fsilu(acch[ob][2] + bh0) * fsig(accg[ob][2] + bg0) * accr[ob][2];
        u[ob][3] = fsilu(acch[ob][3] + bh1) * fsig(accg[ob][3] + bg1) * accr[ob][3];
    }
}

__global__ void __launch_bounds__(THREADS, 1) m3gnet_fused(
    const float* __restrict__ node_feat, const float* __restrict__ edge_feat,
    const float* __restrict__ rbf, const int* __restrict__ src, const int* __restrict__ dst,
    const float* __restrict__ el1w, const float* __restrict__ el1b,
    const float* __restrict__ el2w, const float* __restrict__ el2b,
    const float* __restrict__ eg1w, const float* __restrict__ eg1b,
    const float* __restrict__ eg2w, const float* __restrict__ eg2b,
    const float* __restrict__ nl1w, const float* __restrict__ nl1b,
    const float* __restrict__ nl2w, const float* __restrict__ nl2b,
    const float* __restrict__ ng1w, const float* __restrict__ ng1b,
    const float* __restrict__ ng2w, const float* __restrict__ ng2b,
    const float* __restrict__ eww, const float* __restrict__ nww,
    float* __restrict__ out_e, float* __restrict__ out_v,
    int E)
{
    extern __shared__ char smem[];
    uint8_t* s_w1e8 = (uint8_t*)(smem + B_W1E8);
    __half*  s_w1n  = (__half*)(smem + B_W1N);
    __half*  s_w2e  = (__half*)(smem + B_W2E);
    __half*  s_w2n  = (__half*)(smem + B_W2N);
    __half*  s_wrb  = (__half*)(smem + B_WRB);
    float*   s_b1e  = (float*)(smem + B_B1E);
    float*   s_b2e  = (float*)(smem + B_B2E);
    float*   s_b1n  = (float*)(smem + B_B1N);
    float*   s_b2n  = (float*)(smem + B_B2N);
    __half*  s_x16  = (__half*)(smem + B_X16);
    uint8_t* s_x8   = (uint8_t*)(smem + B_X8);
    __half*  s_rb   = (__half*)(smem + B_RB);

    const int tid = threadIdx.x;

    for (int i = tid; i < NWARP * 16 * LDRB; i += THREADS)
        s_rb[i] = __half(0.0f);

    // W1e -> fp8 x16; W1n -> fp16 (unscaled)
    for (int i = tid; i < 64 * 48; i += THREADS) {     // 4 k at a time (fp8)
        int n = i / 48, k4 = (i - n * 48) * 4;
        const float* pl = el1w + n * 192 + k4;
        const float* pg = eg1w + n * 192 + k4;
        *(uint32_t*)(s_w1e8 + n * LDW8 + k4) =
            f4_e4m3(16*pl[0], 16*pl[1], 16*pl[2], 16*pl[3]);
        *(uint32_t*)(s_w1e8 + (64 + n) * LDW8 + k4) =
            f4_e4m3(16*pg[0], 16*pg[1], 16*pg[2], 16*pg[3]);
    }
    for (int i = tid; i < 64 * 192; i += THREADS) {
        int n = i / 192, k = i - n * 192;
        s_w1n[n * LDK1 + k]        = __float2half(nl1w[i]);
        s_w1n[(64 + n) * LDK1 + k] = __float2half(ng1w[i]);
    }
    for (int i = tid; i < 64 * 64; i += THREADS) {
        int n = i >> 6, k = i & 63;
        s_w2e[n * LDK2 + k]        = __float2half(el2w[i]);
        s_w2e[(64 + n) * LDK2 + k] = __float2half(eg2w[i]);
        s_w2n[n * LDK2 + k]        = __float2half(nl2w[i]);
        s_w2n[(64 + n) * LDK2 + k] = __float2half(ng2w[i]);
    }
    for (int i = tid; i < 128 * 16; i += THREADS) {
        int n = i >> 4, k = i & 15;
        float v = 0.0f;
        if (k < 9) v = (n < 64) ? eww[n * 9 + k] : nww[(n - 64) * 9 + k];
        s_wrb[n * LDKR + k] = __float2half(v);
    }
    if (tid < 64) {
        s_b1e[tid] = el1b[tid]; s_b1e[64 + tid] = eg1b[tid];
        s_b2e[tid] = el2b[tid]; s_b2e[64 + tid] = eg2b[tid];
        s_b1n[tid] = nl1b[tid]; s_b1n[64 + tid] = ng1b[tid];
        s_b2n[tid] = nl2b[tid]; s_b2n[64 + tid] = ng2b[tid];
    }
    __syncthreads();
    // ---- NO block barriers below; each warp autonomous ----

    const int lane = tid & 31;
    const int warp = tid >> 5;
    __half*  xb16 = s_x16 + warp * 16 * LDX;
    uint8_t* xb8  = s_x8  + warp * 16 * LDX8;
    __half*  rb   = s_rb  + warp * 16 * LDRB;
    const int r0 = lane >> 2, cp = (lane & 3) << 1;
    const int srow = lane & 15, sec = lane >> 4;

    const long nwt = ((long)E + 15) >> 4;
    for (long wt = (long)blockIdx.x * NWARP + warp; wt < nwt; wt += (long)gridDim.x * NWARP) {
        const long ebase = wt << 4;

        // ---- stage own 16 edges: X16 = [vi|vj|ef] fp16, X8 = same in e4m3, rbf ----
        {
            const long e = ebase + srow;
            const bool v = e < (long)E;
            __half*  xr  = xb16 + srow * LDX;
            uint8_t* x8r = xb8  + srow * LDX8;
            if (sec == 0) {
                if (v) {
                    const int se = src[e];
                    const float4* vs = (const float4*)(node_feat + (long)se * 64);
                    #pragma unroll
                    for (int j = 0; j < 16; ++j) st4h(xr + j * 4, vs[j]);
                    #pragma unroll
                    for (int j = 0; j < 4; ++j) *(uint4*)(x8r + j * 16) = q16(vs + j * 4);
                    const float4* ef = (const float4*)(edge_feat + e * 64);
                    #pragma unroll
                    for (int j = 0; j < 8; ++j) st4h(xr + 128 + j * 4, ef[j]);
                    #pragma unroll
                    for (int j = 0; j < 2; ++j) *(uint4*)(x8r + 128 + j * 16) = q16(ef + j * 4);
                    #pragma unroll
                    for (int k = 0; k < 9; ++k)
                        rb[srow * LDRB + k] = __float2half(rbf[e * 9 + k]);
                } else {
                    const uint2 z2 = {0u, 0u};
                    const uint4 z4 = {0u,0u,0u,0u};
                    #pragma unroll
                    for (int j = 0; j < 16; ++j) *(uint2*)(xr + j * 4) = z2;
                    #pragma unroll
                    for (int j = 0; j < 8; ++j) *(uint2*)(xr + 128 + j * 4) = z2;
                    #pragma unroll
                    for (int j = 0; j < 4; ++j) *(uint4*)(x8r + j * 16) = z4;
                    #pragma unroll
                    for (int j = 0; j < 2; ++j) *(uint4*)(x8r + 128 + j * 16) = z4;
                    #pragma unroll
                    for (int k = 0; k < 9; ++k) rb[srow * LDRB + k] = __half(0.0f);
                }
            } else {
                if (v) {
                    const int de = dst[e];
                    const float4* vd = (const float4*)(node_feat + (long)de * 64);
                    #pragma unroll
                    for (int j = 0; j < 16; ++j) st4h(xr + 64 + j * 4, vd[j]);
                    #pragma unroll
                    for (int j = 0; j < 4; ++j) *(uint4*)(x8r + 64 + j * 16) = q16(vd + j * 4);
                    const float4* ef = (const float4*)(edge_feat + e * 64);
                    #pragma unroll
                    for (int j = 8; j < 16; ++j) st4h(xr + 128 + j * 4, ef[j]);
                    #pragma unroll
                    for (int j = 2; j < 4; ++j) *(uint4*)(x8r + 128 + j * 16) = q16(ef + j * 4);
                } else {
                    const uint2 z2 = {0u, 0u};
                    const uint4 z4 = {0u,0u,0u,0u};
                    #pragma unroll
                    for (int j = 0; j < 16; ++j) *(uint2*)(xr + 64 + j * 4) = z2;
                    #pragma unroll
                    for (int j = 8; j < 16; ++j) *(uint2*)(xr + 128 + j * 4) = z2;
                    #pragma unroll
                    for (int j = 0; j < 4; ++j) *(uint4*)(x8r + 64 + j * 16) = z4;
                    #pragma unroll
                    for (int j = 2; j < 4; ++j) *(uint4*)(x8r + 128 + j * 16) = z4;
                }
            }
        }

        // prefetch fp32 residuals + dst indices for this thread's output rows
        const long e0 = ebase + r0, e1 = e0 + 8;
        const bool v0 = e0 < (long)E, v1 = e1 < (long)E;
        float2 ef0[8], ef1[8];
        int de0 = 0, de1 = 0;
        if (v0) {
            de0 = dst[e0];
            #pragma unroll
            for (int ob = 0; ob < 8; ++ob)
                ef0[ob] = *(const float2*)(edge_feat + e0 * 64 + ob * 8 + cp);
        }
        if (v1) {
            de1 = dst[e1];
            #pragma unroll
            for (int ob = 0; ob < 8; ++ob)
                ef1[ob] = *(const float2*)(edge_feat + e1 * 64 + ob * 8 + cp);
        }
        __syncwarp();

        uint32_t ah[16], ag[16];
        float u[8][4];

        // ================= EDGE PATH (fp8 GEMM1) =================
        gemm1_e8(xb8, s_w1e8, s_b1e, ah, ag, lane);
        tail_reg<0>(ah, ag, s_w2e, s_b2e, rb, s_wrb, u, lane);
        #pragma unroll
        for (int ob = 0; ob < 8; ++ob) {
            int c = ob * 8 + cp;
            if (v0) {
                float o0 = ef0[ob].x + u[ob][0], o1 = ef0[ob].y + u[ob][1];
                *(float2*)(out_e + e0 * 64 + c) = make_float2(o0, o1);
                *(uint32_t*)(xb16 + r0 * LDX + 128 + c) = h2pack(o0, o1);
            }
            if (v1) {
                float o2 = ef1[ob].x + u[ob][2], o3 = ef1[ob].y + u[ob][3];
                *(float2*)(out_e + e1 * 64 + c) = make_float2(o2, o3);
                *(uint32_t*)(xb16 + (r0 + 8) * LDX + 128 + c) = h2pack(o2, o3);
            }
        }
        __syncwarp();   // e_new patch visible to warp before node GEMM1

        // ================= NODE PATH (full fp16 GEMM1) =================
        gemm1_reg(xb16, s_w1n, s_b1n, ah, ag, lane);
        tail_reg<1>(ah, ag, s_w2n, s_b2n, rb, s_wrb, u, lane);
        #pragma unroll
        for (int ob = 0; ob < 8; ++ob) {
            int c = ob * 8 + cp;
            if (v0)
                asm volatile("red.global.add.v2.f32 [%0], {%1,%2};\n"
                             :: "l"(out_v + (long)de0 * 64 + c), "f"(u[ob][0]), "f"(u[ob][1])
                             : "memory");
            if (v1)
                asm volatile("red.global.add.v2.f32 [%0], {%1,%2};\n"
                             :: "l"(out_v + (long)de1 * 64 + c), "f"(u[ob][2]), "f"(u[ob][3])
                             : "memory");
        }
        __syncwarp();
    }
}

__global__ void copy_v_init(const float* __restrict__ nf, float* __restrict__ outv, int n4)
{
    for (int i = blockIdx.x * blockDim.x + threadIdx.x; i < n4; i += gridDim.x * blockDim.x)
        ((float4*)outv)[i] = ((const float4*)nf)[i];
}

extern "C" void kernel_launch(void* const* d_in, const int* in_sizes, int n_in,
                              void* d_out, int out_size)
{
    const float* node_feat = (const float*)d_in[0];
    const float* edge_feat = (const float*)d_in[1];
    const float* rbf       = (const float*)d_in[2];
    const int*   src       = (const int*)d_in[3];
    const int*   dst       = (const int*)d_in[4];
    const float* el1w = (const float*)d_in[5];  const float* el1b = (const float*)d_in[6];
    const float* el2w = (const float*)d_in[7];  const float* el2b = (const float*)d_in[8];
    const float* eg1w = (const float*)d_in[9];  const float* eg1b = (const float*)d_in[10];
    const float* eg2w = (const float*)d_in[11]; const float* eg2b = (const float*)d_in[12];
    const float* nl1w = (const float*)d_in[13]; const float* nl1b = (const float*)d_in[14];
    const float* nl2w = (const float*)d_in[15]; const float* nl2b = (const float*)d_in[16];
    const float* ng1w = (const float*)d_in[17]; const float* ng1b = (const float*)d_in[18];
    const float* ng2w = (const float*)d_in[19]; const float* ng2b = (const float*)d_in[20];
    const float* eww  = (const float*)d_in[21]; const float* nww  = (const float*)d_in[22];

    const int E = in_sizes[3];
    const int N = in_sizes[0] / 64;
    float* out_e = (float*)d_out;
    float* out_v = out_e + (size_t)E * 64;

    int sms = 148;
    cudaDeviceGetAttribute(&sms, cudaDevAttrMultiProcessorCount, 0);

    cudaFuncSetAttribute(m3gnet_fused, cudaFuncAttributeMaxDynamicSharedMemorySize, SMEM_BYTES);

    copy_v_init<<<sms * 4, 256>>>(node_feat, out_v, N * 16);

    m3gnet_fused<<<sms, THREADS, SMEM_BYTES>>>(
        node_feat, edge_feat, rbf, src, dst,
        el1w, el1b, el2w, el2b, eg1w, eg1b, eg2w, eg2b,
        nl1w, nl1b, nl2w, nl2b, ng1w, ng1b, ng2w, ng2b,
        eww, nww, out_e, out_v, E);
}

// round 15
// speedup vs baseline: 1.0138x; 1.0138x over previous
#include <cuda_runtime.h>
#include <cuda_fp16.h>
#include <cstdint>

// ---------------- constants ----------------
constexpr int THREADS = 256;     // 8 autonomous warps, each owns 16 edges/tile
constexpr int NWARP   = 8;

constexpr int LDX   = 200;  // X16 stride (halfs): 400B
constexpr int LDK1  = 200;  // W1n^T fp16 stride (halfs)
constexpr int LDW8  = 208;  // W1e fp8 stride (bytes)
constexpr int LDX8  = 208;  // X8 stride (bytes)
constexpr int LDK2  = 72;   // W2^T fp16 stride (halfs)
constexpr int LDKR  = 24;   // Wrbf^T stride (halfs)
constexpr int LDRB  = 24;   // rbf activation stride (halfs)

// byte offsets into dynamic smem
constexpr int B_W1E8 = 0;                         // [128 n][208B] fp8 (l|g), x16 scaled
constexpr int B_W1N  = B_W1E8 + 128*LDW8;         // [128 n][200h] fp16 (l|g), K=192
constexpr int B_W2E  = B_W1N  + 128*LDK1*2;       // [128 n][72h] fp16
constexpr int B_W2N  = B_W2E  + 128*LDK2*2;
constexpr int B_WRB  = B_W2N  + 128*LDK2*2;       // [128 n][24h] (We|Wn, k9..15=0)
constexpr int B_B1E  = B_WRB  + 128*LDKR*2;       // [128] float each
constexpr int B_B2E  = B_B1E + 128*4;
constexpr int B_B1N  = B_B2E + 128*4;
constexpr int B_B2N  = B_B1N + 128*4;
constexpr int B_X16  = B_B2N + 128*4;             // 8 x [16][200h] fp16 (vi|vj|ef->e_new)
constexpr int B_X8   = B_X16 + NWARP*16*LDX*2;    // 8 x [16][208B] fp8 (vi|vj|ef)
constexpr int B_RB   = B_X8  + NWARP*16*LDX8;     // 8 x [16][24h]
constexpr int SMEM_BYTES = B_RB + NWARP*16*LDRB*2;  // = 206,848

__device__ __forceinline__ float fsig(float x) {
    float t;
    asm("tanh.approx.f32 %0, %1;\n" : "=f"(t) : "f"(x * 0.5f));
    return fmaf(t, 0.5f, 0.5f);
}
__device__ __forceinline__ float fsilu(float x) { return x * fsig(x); }

__device__ __forceinline__ uint32_t cvta_s(const void* p) {
    return (uint32_t)__cvta_generic_to_shared(p);
}
__device__ __forceinline__ void ldx4(uint32_t* r, uint32_t a) {
    asm volatile("ldmatrix.sync.aligned.m8n8.x4.shared.b16 {%0,%1,%2,%3}, [%4];\n"
                 : "=r"(r[0]), "=r"(r[1]), "=r"(r[2]), "=r"(r[3]) : "r"(a));
}
__device__ __forceinline__ void mma16816(float* c, const uint32_t* a, uint32_t b0, uint32_t b1) {
    asm volatile("mma.sync.aligned.m16n8k16.row.col.f32.f16.f16.f32 "
                 "{%0,%1,%2,%3}, {%4,%5,%6,%7}, {%8,%9}, {%0,%1,%2,%3};\n"
                 : "+f"(c[0]), "+f"(c[1]), "+f"(c[2]), "+f"(c[3])
                 : "r"(a[0]), "r"(a[1]), "r"(a[2]), "r"(a[3]), "r"(b0), "r"(b1));
}
__device__ __forceinline__ void mma16832(float* c, const uint32_t* a, uint32_t b0, uint32_t b1) {
    asm volatile("mma.sync.aligned.m16n8k32.row.col.f32.e4m3.e4m3.f32 "
                 "{%0,%1,%2,%3}, {%4,%5,%6,%7}, {%8,%9}, {%0,%1,%2,%3};\n"
                 : "+f"(c[0]), "+f"(c[1]), "+f"(c[2]), "+f"(c[3])
                 : "r"(a[0]), "r"(a[1]), "r"(a[2]), "r"(a[3]), "r"(b0), "r"(b1));
}
__device__ __forceinline__ uint32_t h2pack(float a, float b) {
    __half2 h = __floats2half2_rn(a, b);
    return *(uint32_t*)&h;
}
__device__ __forceinline__ void st4h(__half* p, float4 v) {
    uint2 u;
    u.x = h2pack(v.x, v.y);
    u.y = h2pack(v.z, v.w);
    *(uint2*)p = u;
}
// pack 4 floats -> 4 e4m3 bytes (byte0 = a)
__device__ __forceinline__ uint32_t f4_e4m3(float a, float b, float c, float d) {
    uint16_t lo, hi;
    asm("cvt.rn.satfinite.e4m3x2.f32 %0, %1, %2;" : "=h"(lo) : "f"(b), "f"(a));
    asm("cvt.rn.satfinite.e4m3x2.f32 %0, %1, %2;" : "=h"(hi) : "f"(d), "f"(c));
    return (uint32_t)lo | ((uint32_t)hi << 16);
}
__device__ __forceinline__ uint4 q16(const float4* v) {
    uint4 o;
    float4 a = v[0], b = v[1], c = v[2], d = v[3];
    o.x = f4_e4m3(a.x, a.y, a.z, a.w);
    o.y = f4_e4m3(b.x, b.y, b.z, b.w);
    o.z = f4_e4m3(c.x, c.y, c.z, c.w);
    o.w = f4_e4m3(d.x, d.y, d.z, d.w);
    return o;
}

// ================= EDGE GEMM1: fp8, m16 x n128 x k192 (6 kt of k32) ==========
__device__ __forceinline__ void gemm1_e8(const uint8_t* X8, const uint8_t* W8,
                                         const float* b1, uint32_t* ah, uint32_t* ag, int lane)
{
    float acc[16][4];
    #pragma unroll
    for (int n = 0; n < 16; ++n)
        #pragma unroll
        for (int j = 0; j < 4; ++j) acc[n][j] = 0.0f;

    uint32_t aB = cvta_s(X8 + (lane & 15) * LDX8 + ((lane >> 4) << 4));
    const int n_off = (lane & 7) + ((lane >> 4) << 3);
    const int k_off = ((lane >> 3) & 1) << 4;
    uint32_t bB = cvta_s(W8 + n_off * LDW8 + k_off);

    #pragma unroll
    for (int kt = 0; kt < 6; ++kt) {
        uint32_t a[4];
        ldx4(a, aB + kt * 32);
        #pragma unroll
        for (int nb2 = 0; nb2 < 8; ++nb2) {
            uint32_t b[4];
            ldx4(b, bB + nb2 * 16 * LDW8 + kt * 32);
            mma16832(acc[2*nb2],     a, b[0], b[1]);
            mma16832(acc[2*nb2 + 1], a, b[2], b[3]);
        }
    }

    const int cp = (lane & 3) << 1;
    #pragma unroll
    for (int nb = 0; nb < 16; ++nb) {
        int c = nb * 8 + cp;
        float v0 = fsilu(fmaf(acc[nb][0], 0.0625f, b1[c]));
        float v1 = fsilu(fmaf(acc[nb][1], 0.0625f, b1[c + 1]));
        float v2 = fsilu(fmaf(acc[nb][2], 0.0625f, b1[c]));
        float v3 = fsilu(fmaf(acc[nb][3], 0.0625f, b1[c + 1]));
        uint32_t* dstv = (nb < 8) ? ah : ag;
        int kb = (nb & 7) >> 1, odd = nb & 1;
        dstv[kb*4 + odd*2 + 0] = h2pack(v0, v1);
        dstv[kb*4 + odd*2 + 1] = h2pack(v2, v3);
    }
}

// ================= NODE GEMM1: fp16, m16 x n128 x k192 (champion code) =======
__device__ __forceinline__ void gemm1_reg(const __half* X, const __half* W1,
                                          const float* bias,
                                          uint32_t* ah, uint32_t* ag, int lane)
{
    float acc[16][4];
    #pragma unroll
    for (int n = 0; n < 16; ++n)
        #pragma unroll
        for (int j = 0; j < 4; ++j) acc[n][j] = 0.0f;

    uint32_t aB = cvta_s(X + (lane & 15) * LDX + ((lane >> 4) << 3));
    const int n_off = (lane & 7) + ((lane >> 4) << 3);
    const int k_off = ((lane >> 3) & 1) << 3;
    uint32_t bB = cvta_s(W1 + n_off * LDK1 + k_off);

    #pragma unroll
    for (int kt = 0; kt < 12; ++kt) {
        uint32_t a[4];
        ldx4(a, aB + kt * 32);
        #pragma unroll
        for (int nb2 = 0; nb2 < 8; ++nb2) {
            uint32_t b[4];
            ldx4(b, bB + (nb2 * 16 * LDK1 + kt * 16) * 2);
            mma16816(acc[2*nb2],     a, b[0], b[1]);
            mma16816(acc[2*nb2 + 1], a, b[2], b[3]);
        }
    }

    const int cp = (lane & 3) << 1;
    #pragma unroll
    for (int nb = 0; nb < 16; ++nb) {
        int c = nb * 8 + cp;
        float v0 = fsilu(acc[nb][0] + bias[c]);
        float v1 = fsilu(acc[nb][1] + bias[c + 1]);
        float v2 = fsilu(acc[nb][2] + bias[c]);
        float v3 = fsilu(acc[nb][3] + bias[c + 1]);
        uint32_t* dstv = (nb < 8) ? ah : ag;
        int kb = (nb & 7) >> 1, odd = nb & 1;
        dstv[kb*4 + odd*2 + 0] = h2pack(v0, v1);
        dstv[kb*4 + odd*2 + 1] = h2pack(v2, v3);
    }
}

// GEMM2 (H & G, A in regs) + rbf mini-GEMM + gate combine (champion code).
template <int PATH>
__device__ __forceinline__ void tail_reg(const uint32_t* ah, const uint32_t* ag,
                                         const __half* W2, const float* b2,
                                         const __half* RB, const __half* WRB,
                                         float u[8][4], int lane)
{
    float acch[8][4], accg[8][4];
    #pragma unroll
    for (int n = 0; n < 8; ++n)
        #pragma unroll
        for (int j = 0; j < 4; ++j) { acch[n][j] = 0; accg[n][j] = 0; }

    const int n_off = (lane & 7) + ((lane >> 4) << 3);
    const int k_off = ((lane >> 3) & 1) << 3;
    uint32_t bB = cvta_s(W2 + n_off * LDK2 + k_off);

    #pragma unroll
    for (int kt = 0; kt < 4; ++kt) {
        #pragma unroll
        for (int nb2 = 0; nb2 < 4; ++nb2) {
            uint32_t b[4];
            ldx4(b, bB + (nb2 * 16 * LDK2 + kt * 16) * 2);
            mma16816(acch[2*nb2],     ah + kt*4, b[0], b[1]);
            mma16816(acch[2*nb2 + 1], ah + kt*4, b[2], b[3]);
        }
        #pragma unroll
        for (int nb2 = 0; nb2 < 4; ++nb2) {
            uint32_t b[4];
            ldx4(b, bB + ((64 + nb2 * 16) * LDK2 + kt * 16) * 2);
            mma16816(accg[2*nb2],     ag + kt*4, b[0], b[1]);
            mma16816(accg[2*nb2 + 1], ag + kt*4, b[2], b[3]);
        }
    }

    float accr[8][4];
    #pragma unroll
    for (int n = 0; n < 8; ++n)
        #pragma unroll
        for (int j = 0; j < 4; ++j) accr[n][j] = 0;
    {
        uint32_t ar[4];
        ldx4(ar, cvta_s(RB + (lane & 15) * LDRB + ((lane >> 4) << 3)));
        uint32_t bR = cvta_s(WRB + (PATH * 64 + n_off) * LDKR + k_off);
        #pragma unroll
        for (int nb2 = 0; nb2 < 4; ++nb2) {
            uint32_t b[4];
            ldx4(b, bR + (nb2 * 16 * LDKR) * 2);
            mma16816(accr[2*nb2],     ar, b[0], b[1]);
            mma16816(accr[2*nb2 + 1], ar, b[2], b[3]);
        }
    }

    const int cp = (lane & 3) << 1;
    #pragma unroll
    for (int ob = 0; ob < 8; ++ob) {
        int c = ob * 8 + cp;
        float bh0 = b2[c], bh1 = b2[c + 1];
        float bg0 = b2[64 + c], bg1 = b2[64 + c + 1];
        u[ob][0] = fsilu(acch[ob][0] + bh0) * fsig(accg[ob][0] + bg0) * accr[ob][0];
        u[ob][1] = fsilu(acch[ob][1] + bh1) * fsig(accg[ob][1] + bg1) * accr[ob][1];
        u[ob][2] = fsilu(acch[ob][2] + bh0) * fsig(accg[ob][2] + bg0) * accr[ob][2];
        u[ob][3] = fsilu(acch[ob][3] + bh1) * fsig(accg[ob][3] + bg1) * accr[ob][3];
    }
}

__global__ void __launch_bounds__(THREADS, 1) m3gnet_fused(
    const float* __restrict__ node_feat, const float* __restrict__ edge_feat,
    const float* __restrict__ rbf, const int* __restrict__ src, const int* __restrict__ dst,
    const float* __restrict__ el1w, const float* __restrict__ el1b,
    const float* __restrict__ el2w, const float* __restrict__ el2b,
    const float* __restrict__ eg1w, const float* __restrict__ eg1b,
    const float* __restrict__ eg2w, const float* __restrict__ eg2b,
    const float* __restrict__ nl1w, const float* __restrict__ nl1b,
    const float* __restrict__ nl2w, const float* __restrict__ nl2b,
    const float* __restrict__ ng1w, const float* __restrict__ ng1b,
    const float* __restrict__ ng2w, const float* __restrict__ ng2b,
    const float* __restrict__ eww, const float* __restrict__ nww,
    float* __restrict__ out_e, float* __restrict__ out_v,
    int E)
{
    extern __shared__ char smem[];
    uint8_t* s_w1e8 = (uint8_t*)(smem + B_W1E8);
    __half*  s_w1n  = (__half*)(smem + B_W1N);
    __half*  s_w2e  = (__half*)(smem + B_W2E);
    __half*  s_w2n  = (__half*)(smem + B_W2N);
    __half*  s_wrb  = (__half*)(smem + B_WRB);
    float*   s_b1e  = (float*)(smem + B_B1E);
    float*   s_b2e  = (float*)(smem + B_B2E);
    float*   s_b1n  = (float*)(smem + B_B1N);
    float*   s_b2n  = (float*)(smem + B_B2N);
    __half*  s_x16  = (__half*)(smem + B_X16);
    uint8_t* s_x8   = (uint8_t*)(smem + B_X8);
    __half*  s_rb   = (__half*)(smem + B_RB);

    const int tid = threadIdx.x;

    for (int i = tid; i < NWARP * 16 * LDRB; i += THREADS)
        s_rb[i] = __half(0.0f);

    // W1e -> fp8 x16; W1n -> fp16
    for (int i = tid; i < 64 * 48; i += THREADS) {
        int n = i / 48, k4 = (i - n * 48) * 4;
        const float* pl = el1w + n * 192 + k4;
        const float* pg = eg1w + n * 192 + k4;
        *(uint32_t*)(s_w1e8 + n * LDW8 + k4) =
            f4_e4m3(16*pl[0], 16*pl[1], 16*pl[2], 16*pl[3]);
        *(uint32_t*)(s_w1e8 + (64 + n) * LDW8 + k4) =
            f4_e4m3(16*pg[0], 16*pg[1], 16*pg[2], 16*pg[3]);
    }
    for (int i = tid; i < 64 * 192; i += THREADS) {
        int n = i / 192, k = i - n * 192;
        s_w1n[n * LDK1 + k]        = __float2half(nl1w[i]);
        s_w1n[(64 + n) * LDK1 + k] = __float2half(ng1w[i]);
    }
    for (int i = tid; i < 64 * 64; i += THREADS) {
        int n = i >> 6, k = i & 63;
        s_w2e[n * LDK2 + k]        = __float2half(el2w[i]);
        s_w2e[(64 + n) * LDK2 + k] = __float2half(eg2w[i]);
        s_w2n[n * LDK2 + k]        = __float2half(nl2w[i]);
        s_w2n[(64 + n) * LDK2 + k] = __float2half(ng2w[i]);
    }
    for (int i = tid; i < 128 * 16; i += THREADS) {
        int n = i >> 4, k = i & 15;
        float v = 0.0f;
        if (k < 9) v = (n < 64) ? eww[n * 9 + k] : nww[(n - 64) * 9 + k];
        s_wrb[n * LDKR + k] = __float2half(v);
    }
    if (tid < 64) {
        s_b1e[tid] = el1b[tid]; s_b1e[64 + tid] = eg1b[tid];
        s_b2e[tid] = el2b[tid]; s_b2e[64 + tid] = eg2b[tid];
        s_b1n[tid] = nl1b[tid]; s_b1n[64 + tid] = ng1b[tid];
        s_b2n[tid] = nl2b[tid]; s_b2n[64 + tid] = ng2b[tid];
    }
    __syncthreads();
    // ---- NO block barriers below; each warp autonomous ----

    const int lane = tid & 31;
    const int warp = tid >> 5;
    __half*  xb16 = s_x16 + warp * 16 * LDX;
    uint8_t* xb8  = s_x8  + warp * 16 * LDX8;
    __half*  rb   = s_rb  + warp * 16 * LDRB;
    const int r0 = lane >> 2, cp = (lane & 3) << 1;
    const int srow = lane & 15, sec = lane >> 4;

    const long nwt = ((long)E + 15) >> 4;
    for (long wt = (long)blockIdx.x * NWARP + warp; wt < nwt; wt += (long)gridDim.x * NWARP) {
        const long ebase = wt << 4;

        // ---- stage own 16 edges: X16 fp16, X8 e4m3, rbf fp16 ----
        {
            const long e = ebase + srow;
            const bool v = e < (long)E;
            __half*  xr  = xb16 + srow * LDX;
            uint8_t* x8r = xb8  + srow * LDX8;
            if (sec == 0) {
                if (v) {
                    const int se = src[e];
                    const float4* vs = (const float4*)(node_feat + (long)se * 64);
                    #pragma unroll
                    for (int j = 0; j < 16; ++j) st4h(xr + j * 4, vs[j]);
                    #pragma unroll
                    for (int j = 0; j < 4; ++j) *(uint4*)(x8r + j * 16) = q16(vs + j * 4);
                    const float4* ef = (const float4*)(edge_feat + e * 64);
                    #pragma unroll
                    for (int j = 0; j < 8; ++j) st4h(xr + 128 + j * 4, ef[j]);
                    #pragma unroll
                    for (int j = 0; j < 2; ++j) *(uint4*)(x8r + 128 + j * 16) = q16(ef + j * 4);
                    #pragma unroll
                    for (int k = 0; k < 9; ++k)
                        rb[srow * LDRB + k] = __float2half(rbf[e * 9 + k]);
                } else {
                    const uint2 z2 = {0u, 0u};
                    const uint4 z4 = {0u,0u,0u,0u};
                    #pragma unroll
                    for (int j = 0; j < 16; ++j) *(uint2*)(xr + j * 4) = z2;
                    #pragma unroll
                    for (int j = 0; j < 8; ++j) *(uint2*)(xr + 128 + j * 4) = z2;
                    #pragma unroll
                    for (int j = 0; j < 4; ++j) *(uint4*)(x8r + j * 16) = z4;
                    #pragma unroll
                    for (int j = 0; j < 2; ++j) *(uint4*)(x8r + 128 + j * 16) = z4;
                    #pragma unroll
                    for (int k = 0; k < 9; ++k) rb[srow * LDRB + k] = __half(0.0f);
                }
            } else {
                if (v) {
                    const int de = dst[e];
                    const float4* vd = (const float4*)(node_feat + (long)de * 64);
                    #pragma unroll
                    for (int j = 0; j < 16; ++j) st4h(xr + 64 + j * 4, vd[j]);
                    #pragma unroll
                    for (int j = 0; j < 4; ++j) *(uint4*)(x8r + 64 + j * 16) = q16(vd + j * 4);
                    const float4* ef = (const float4*)(edge_feat + e * 64);
                    #pragma unroll
                    for (int j = 8; j < 16; ++j) st4h(xr + 128 + j * 4, ef[j]);
                    #pragma unroll
                    for (int j = 2; j < 4; ++j) *(uint4*)(x8r + 128 + j * 16) = q16(ef + j * 4);
                } else {
                    const uint2 z2 = {0u, 0u};
                    const uint4 z4 = {0u,0u,0u,0u};
                    #pragma unroll
                    for (int j = 0; j < 16; ++j) *(uint2*)(xr + 64 + j * 4) = z2;
                    #pragma unroll
                    for (int j = 8; j < 16; ++j) *(uint2*)(xr + 128 + j * 4) = z2;
                    #pragma unroll
                    for (int j = 0; j < 4; ++j) *(uint4*)(x8r + 64 + j * 16) = z4;
                    #pragma unroll
                    for (int j = 2; j < 4; ++j) *(uint4*)(x8r + 128 + j * 16) = z4;
                }
            }
        }
        __syncwarp();

        const long e0 = ebase + r0, e1 = e0 + 8;
        const bool v0 = e0 < (long)E, v1 = e1 < (long)E;

        uint32_t ah[16], ag[16];
        float u[8][4];

        // ================= EDGE PATH (fp8 GEMM1) =================
        gemm1_e8(xb8, s_w1e8, s_b1e, ah, ag, lane);
        tail_reg<0>(ah, ag, s_w2e, s_b2e, rb, s_wrb, u, lane);
        #pragma unroll
        for (int ob = 0; ob < 8; ++ob) {
            int c = ob * 8 + cp;
            if (v0) {
                float2 ef = *(const float2*)(edge_feat + e0 * 64 + c);
                float o0 = ef.x + u[ob][0], o1 = ef.y + u[ob][1];
                *(float2*)(out_e + e0 * 64 + c) = make_float2(o0, o1);
                *(uint32_t*)(xb16 + r0 * LDX + 128 + c) = h2pack(o0, o1);
            }
            if (v1) {
                float2 ef = *(const float2*)(edge_feat + e1 * 64 + c);
                float o2 = ef.x + u[ob][2], o3 = ef.y + u[ob][3];
                *(float2*)(out_e + e1 * 64 + c) = make_float2(o2, o3);
                *(uint32_t*)(xb16 + (r0 + 8) * LDX + 128 + c) = h2pack(o2, o3);
            }
        }
        __syncwarp();   // e_new patch visible to warp before node GEMM1

        // ================= NODE PATH (full fp16 GEMM1) =================
        gemm1_reg(xb16, s_w1n, s_b1n, ah, ag, lane);
        tail_reg<1>(ah, ag, s_w2n, s_b2n, rb, s_wrb, u, lane);
        {
            const int de0 = v0 ? dst[e0] : 0;
            const int de1 = v1 ? dst[e1] : 0;
            #pragma unroll
            for (int ob = 0; ob < 8; ++ob) {
                int c = ob * 8 + cp;
                if (v0)
                    asm volatile("red.global.add.v2.f32 [%0], {%1,%2};\n"
                                 :: "l"(out_v + (long)de0 * 64 + c), "f"(u[ob][0]), "f"(u[ob][1])
                                 : "memory");
                if (v1)
                    asm volatile("red.global.add.v2.f32 [%0], {%1,%2};\n"
                                 :: "l"(out_v + (long)de1 * 64 + c), "f"(u[ob][2]), "f"(u[ob][3])
                                 : "memory");
            }
        }
        __syncwarp();
    }
}

__global__ void copy_v_init(const float* __restrict__ nf, float* __restrict__ outv, int n4)
{
    for (int i = blockIdx.x * blockDim.x + threadIdx.x; i < n4; i += gridDim.x * blockDim.x)
        ((float4*)outv)[i] = ((const float4*)nf)[i];
}

extern "C" void kernel_launch(void* const* d_in, const int* in_sizes, int n_in,
                              void* d_out, int out_size)
{
    const float* node_feat = (const float*)d_in[0];
    const float* edge_feat = (const float*)d_in[1];
    const float* rbf       = (const float*)d_in[2];
    const int*   src       = (const int*)d_in[3];
    const int*   dst       = (const int*)d_in[4];
    const float* el1w = (const float*)d_in[5];  const float* el1b = (const float*)d_in[6];
    const float* el2w = (const float*)d_in[7];  const float* el2b = (const float*)d_in[8];
    const float* eg1w = (const float*)d_in[9];  const float* eg1b = (const float*)d_in[10];
    const float* eg2w = (const float*)d_in[11]; const float* eg2b = (const float*)d_in[12];
    const float* nl1w = (const float*)d_in[13]; const float* nl1b = (const float*)d_in[14];
    const float* nl2w = (const float*)d_in[15]; const float* nl2b = (const float*)d_in[16];
    const float* ng1w = (const float*)d_in[17]; const float* ng1b = (const float*)d_in[18];
    const float* ng2w = (const float*)d_in[19]; const float* ng2b = (const float*)d_in[20];
    const float* eww  = (const float*)d_in[21]; const float* nww  = (const float*)d_in[22];

    const int E = in_sizes[3];
    const int N = in_sizes[0] / 64;
    float* out_e = (float*)d_out;
    float* out_v = out_e + (size_t)E * 64;

    int sms = 148;
    cudaDeviceGetAttribute(&sms, cudaDevAttrMultiProcessorCount, 0);

    cudaFuncSetAttribute(m3gnet_fused, cudaFuncAttributeMaxDynamicSharedMemorySize, SMEM_BYTES);

    copy_v_init<<<sms * 4, 256>>>(node_feat, out_v, N * 16);

    m3gnet_fused<<<sms, THREADS, SMEM_BYTES>>>(
        node_feat, edge_feat, rbf, src, dst,
        el1w, el1b, el2w, el2b, eg1w, eg1b, eg2w, eg2b,
        nl1w, nl1b, nl2w, nl2b, ng1w, ng1b, ng2w, ng2b,
        eww, nww, out_e, out_v, E);
}